// round 8
// baseline (speedup 1.0000x reference)
#include <cuda_runtime.h>
#include <cuda_bf16.h>
#include <math.h>
#include <stdint.h>

// Problem constants
#define B_ 256
#define T_ 2048
#define C_ 12
#define K_ 4
#define L_ 8
#define FEAT_ 64
#define HID_ 128
#define NCLS_ 10
#define N2_ 1024
#define TR_ 1025
#define EPS_ 1e-5f
#define NBMAX_ 32

typedef unsigned long long ull;

// ---------------------------------------------------------------------------
// Device scratch (static; no runtime allocation)
// ---------------------------------------------------------------------------
__device__ float g_filt[K_ * TR_];
__device__ float d_modes[(size_t)K_ * B_ * C_ * T_];             // 96 MB
__device__ float d_h1[(size_t)K_ * B_ * 32 * T_];                // 256 MB
__device__ float d_h2[(size_t)K_ * B_ * 64 * T_];                // 512 MB
__device__ float d_h3[(size_t)K_ * B_ * 64 * T_];                // 512 MB
__device__ float d_psum[(size_t)K_ * 64 * B_ * NBMAX_];
__device__ float d_psq[(size_t)K_ * 64 * B_ * NBMAX_];
__device__ float d_mean[K_ * 64];
__device__ float d_rstd[K_ * 64];
__device__ float d_feats[B_ * K_ * FEAT_];
// weight pairs (w,w), layout [km][ci*KS+dk][co]
__device__ __align__(16) ull d_w2_1[K_ * 12 * 7 * 32];
__device__ __align__(16) ull d_w2_2[K_ * 32 * 5 * 64];
__device__ __align__(16) ull d_w2_3[K_ * 64 * 3 * 64];

// ---------------------------------------------------------------------------
// Packed f32x2 helpers
// ---------------------------------------------------------------------------
__device__ __forceinline__ ull pack2(float lo, float hi) {
    ull r; asm("mov.b64 %0, {%1, %2};" : "=l"(r) : "f"(lo), "f"(hi)); return r;
}
__device__ __forceinline__ float2 u2f(ull v) {
    float2 f; asm("mov.b64 {%0, %1}, %2;" : "=f"(f.x), "=f"(f.y) : "l"(v)); return f;
}
__device__ __forceinline__ ull fma2(ull a, ull b, ull c) {
    ull d; asm("fma.rn.f32x2 %0, %1, %2, %3;" : "=l"(d) : "l"(a), "l"(b), "l"(c)); return d;
}
__device__ __forceinline__ ull add2(ull a, ull b) {
    ull d; asm("add.rn.f32x2 %0, %1, %2;" : "=l"(d) : "l"(a), "l"(b)); return d;
}

// ---------------------------------------------------------------------------
// 1. UVMD frequency-domain filters g_k(f) (scan is linear in f_hat).
// ---------------------------------------------------------------------------
__device__ __forceinline__ float softplusf(float x) {
    if (x > 20.f) return x;
    return log1pf(expf(x));
}

__global__ __launch_bounds__(128) void g_kernel(
        const float* __restrict__ log_alpha,
        const float* __restrict__ raw_tau,
        const float* __restrict__ raw_omega) {
    float om[K_];
#pragma unroll
    for (int k = 0; k < K_; k++) om[k] = 0.5f / (1.0f + expf(-raw_omega[k]));
    int f = blockIdx.x * blockDim.x + threadIdx.x;
    if (f >= TR_) return;
    float fr = 0.5f * (float)f / 1024.0f;
    float u[K_] = {0.f, 0.f, 0.f, 0.f};
    float lam = 0.f;
    for (int l = 0; l < L_; l++) {
        float tau_l = softplusf(raw_tau[l]);
        float us = u[0] + u[1] + u[2] + u[3];
        float nu[K_], ns = 0.f;
#pragma unroll
        for (int k = 0; k < K_; k++) {
            float a = expf(log_alpha[l * K_ + k]);
            float d = fr - om[k];
            float num = 1.0f - (us - u[k]) + 0.5f * lam;
            nu[k] = num / (1.0f + 2.0f * a * d * d);
            ns += nu[k];
        }
#pragma unroll
        for (int k = 0; k < K_; k++) u[k] = nu[k];
        lam += tau_l * (1.0f - ns);
    }
#pragma unroll
    for (int k = 0; k < K_; k++) g_filt[k * TR_ + f] = u[k];
}

// ---------------------------------------------------------------------------
// 2. Fused rfft -> filter -> irfft per (b,c) signal; writes modes (K,B,C,T).
// ---------------------------------------------------------------------------
__device__ __forceinline__ void fft1024(float* zr, float* zi,
                                        const float* twr, const float* twi,
                                        float dir, int tid) {
#pragma unroll
    for (int s = 0; s < 10; s++) {
        int half = 1 << s;
        int shift = 9 - s;
#pragma unroll
        for (int rep = 0; rep < 2; rep++) {
            int i = tid + rep * 256;
            int pos = i & (half - 1);
            int blk = i >> s;
            int i1 = (blk << (s + 1)) + pos;
            int i2 = i1 + half;
            int ti = pos << shift;
            float c = twr[ti];
            float sn = dir * twi[ti];
            float x2r = zr[i2], x2i = zi[i2];
            float tr = c * x2r - sn * x2i;
            float tim = sn * x2r + c * x2i;
            float x1r = zr[i1], x1i = zi[i1];
            zr[i2] = x1r - tr; zi[i2] = x1i - tim;
            zr[i1] = x1r + tr; zi[i1] = x1i + tim;
        }
        __syncthreads();
    }
}

__global__ __launch_bounds__(256) void uvmd_kernel(const float* __restrict__ x) {
    __shared__ float twr[512], twi[512];
    __shared__ float zr[N2_], zi[N2_];
    __shared__ float Xr[TR_], Xi[TR_];
    int tid = threadIdx.x;
    int sig = blockIdx.x;
    int b = sig / C_, c = sig % C_;

    for (int j = tid; j < 512; j += 256) {
        float ang = (float)M_PI * (float)j / 512.0f;
        twr[j] = cosf(ang);
        twi[j] = -sinf(ang);
    }
    const float* xb = x + (size_t)b * T_ * C_ + c;
    for (int n = tid; n < N2_; n += 256) {
        int j = __brev((unsigned)n) >> 22;
        zr[n] = xb[(size_t)(2 * j) * C_];
        zi[n] = xb[(size_t)(2 * j + 1) * C_];
    }
    __syncthreads();
    fft1024(zr, zi, twr, twi, 1.0f, tid);

    for (int k = tid; k < N2_; k += 256) {
        if (k == 0) {
            Xr[0] = zr[0] + zi[0];   Xi[0] = 0.f;
            Xr[N2_] = zr[0] - zi[0]; Xi[N2_] = 0.f;
        } else {
            float ar = zr[k], ai = zi[k];
            float br = zr[N2_ - k], bi = -zi[N2_ - k];
            float er = 0.5f * (ar + br), ei = 0.5f * (ai + bi);
            float dr = 0.5f * (ar - br), di = 0.5f * (ai - bi);
            float or_ = di, oi = -dr;
            float s_, c_;
            __sincosf(-(float)M_PI * (float)k / 1024.0f, &s_, &c_);
            Xr[k] = er + c_ * or_ - s_ * oi;
            Xi[k] = ei + s_ * or_ + c_ * oi;
        }
    }
    __syncthreads();

    const float invn = 1.0f / 1024.0f;
    for (int km = 0; km < K_; km++) {
        const float* g = g_filt + km * TR_;
        for (int n = tid; n < N2_; n += 256) {
            int k = __brev((unsigned)n) >> 22;
            float vr, vi;
            if (k == 0) {
                float y0 = g[0] * Xr[0];
                float y1 = g[N2_] * Xr[N2_];
                vr = 0.5f * (y0 + y1);
                vi = 0.5f * (y0 - y1);
            } else {
                float gk = g[k], gm = g[N2_ - k];
                float yr = gk * Xr[k], yi = gk * Xi[k];
                float mr = gm * Xr[N2_ - k], mi = -(gm * Xi[N2_ - k]);
                float er = 0.5f * (yr + mr), ei = 0.5f * (yi + mi);
                float dr = 0.5f * (yr - mr), di = 0.5f * (yi - mi);
                float s_, c_;
                __sincosf((float)M_PI * (float)k / 1024.0f, &s_, &c_);
                float or_ = c_ * dr - s_ * di;
                float oi  = s_ * dr + c_ * di;
                vr = er - oi;
                vi = ei + or_;
            }
            zr[n] = vr; zi[n] = vi;
        }
        __syncthreads();
        fft1024(zr, zi, twr, twi, -1.0f, tid);
        float* orow = d_modes + ((((size_t)km * B_ + b) * C_ + c)) * T_;
        for (int n = tid; n < N2_; n += 256) {
            float2 v = make_float2(zr[n] * invn, zi[n] * invn);
            *reinterpret_cast<float2*>(orow + 2 * n) = v;
        }
        __syncthreads();
    }
}

// ---------------------------------------------------------------------------
// 2b. Weight repack: (w,w) pairs in layout [km][ci*KS+dk][co].
// ---------------------------------------------------------------------------
template <int CIN, int COUT, int KS>
__device__ __forceinline__ void wrepack_one(const float* __restrict__ w,
                                            ull* __restrict__ dst, int i) {
    const int n = K_ * CIN * KS * COUT;
    if (i >= n) return;
    int km = i / (CIN * KS * COUT);
    int r = i % (CIN * KS * COUT);
    int tap = r / COUT;
    int co = r % COUT;
    int ci = tap / KS;
    int dk = tap % KS;
    float v = w[(((size_t)km * COUT + co) * CIN + ci) * KS + dk];
    dst[i] = pack2(v, v);
}

__global__ __launch_bounds__(256) void wprep_kernel(
    const float* __restrict__ w1, const float* __restrict__ w2,
    const float* __restrict__ w3) {
    int i = blockIdx.x * blockDim.x + threadIdx.x;
    wrepack_one<12, 32, 7>(w1, d_w2_1, i);
    wrepack_one<32, 64, 5>(w2, d_w2_2, i);
    wrepack_one<64, 64, 3>(w3, d_w2_3, i);
}

// ---------------------------------------------------------------------------
// 3. Conv1d: single aligned cluster per thread (CO=4 channels x 4 t).
//    Window = KS+3 floats via 2-3 LDS.128 (PAD folded into smem base so the
//    cluster base 4h is 16B-aligned). f32x2 math; <=KS+2 ALU packs per ci.
//    Fused input BN+ReLU + fused BN-stat partials.
//    blockDim = 256 = (COUT/4) * (TILE/4). gridDim = (T/TILE, B, K).
// ---------------------------------------------------------------------------
template <int CIN, int COUT, int KS, int TILE, int NB>
__global__ __launch_bounds__(256) void conv_kernel(
    const float* __restrict__ in, const ull* __restrict__ w2g,
    const float* __restrict__ bias,
    const float* __restrict__ bng, const float* __restrict__ bnb,
    const float* __restrict__ mean, const float* __restrict__ rstd,
    float* __restrict__ out, float* __restrict__ psum, float* __restrict__ psq,
    int apply_bn)
{
    constexpr int CO = 4;
    constexpr int PAD = KS / 2;
    constexpr int G = TILE / 4;           // threads per co-group
    constexpr int NG = COUT / CO;         // co-groups
    static_assert(G * NG == 256, "block size");
    constexpr int IW = TILE + KS - 1;     // loaded window (local 0..IW-1)
    constexpr int IWP = TILE + 16;        // padded row stride (floats, mult 4)
    constexpr int NF4 = (KS + 6) / 4;     // float4 loads (window KS+3 floats)
    constexpr int NPR = KS + 2;           // operand pairs (f[j], f[j+1])
    __shared__ __align__(16) float s_in[CIN][IWP];
    __shared__ float s_a[CIN], s_c[CIN];

    int tx = threadIdx.x;
    int b = blockIdx.y;
    int km = blockIdx.z;
    int t0 = blockIdx.x * TILE;
    const float* inb = in + (((size_t)km * B_ + b) * CIN) * T_;

    if (apply_bn) {
        for (int ci = tx; ci < CIN; ci += 256) {
            float a = bng[km * CIN + ci] * rstd[km * 64 + ci];
            s_a[ci] = a;
            s_c[ci] = bnb[km * CIN + ci] - a * mean[km * 64 + ci];
        }
        __syncthreads();
    }
    for (int idx = tx; idx < CIN * IW; idx += 256) {
        int ci = idx / IW, tl = idx % IW;
        int t = t0 + tl - PAD;
        float v = 0.f;
        if (t >= 0 && t < T_) {
            v = inb[(size_t)ci * T_ + t];
            if (apply_bn) v = fmaxf(fmaf(s_a[ci], v, s_c[ci]), 0.f);
        }
        s_in[ci][tl] = v;
    }
    __syncthreads();

    int h = tx % G;
    int cog = tx / G;
    int co0 = cog * CO;
    int tb = 4 * h;                       // local float base (16B aligned)

    ull acc[CO][2];
#pragma unroll
    for (int co = 0; co < CO; co++) {
        float bsv = bias[km * COUT + co0 + co];
        acc[co][0] = pack2(bsv, bsv);
        acc[co][1] = acc[co][0];
    }

    const ull* wb = w2g + (size_t)km * CIN * KS * COUT + co0;
    for (int ci = 0; ci < CIN; ci++) {
        float f[NF4 * 4];
        const float4* p = reinterpret_cast<const float4*>(&s_in[ci][tb]);
#pragma unroll
        for (int q = 0; q < NF4; q++) {
            float4 v = p[q];
            f[4 * q] = v.x; f[4 * q + 1] = v.y;
            f[4 * q + 2] = v.z; f[4 * q + 3] = v.w;
        }
        ull pr[NPR];
#pragma unroll
        for (int j = 0; j < NPR; j++) pr[j] = pack2(f[j], f[j + 1]);
        const ull* wci = wb + (size_t)ci * KS * COUT;
#pragma unroll
        for (int dk = 0; dk < KS; dk++) {
            ulonglong2 w01 = __ldg(reinterpret_cast<const ulonglong2*>(
                wci + (size_t)dk * COUT));
            ulonglong2 w23 = __ldg(reinterpret_cast<const ulonglong2*>(
                wci + (size_t)dk * COUT + 2));
            acc[0][0] = fma2(pr[dk], w01.x, acc[0][0]);
            acc[0][1] = fma2(pr[dk + 2], w01.x, acc[0][1]);
            acc[1][0] = fma2(pr[dk], w01.y, acc[1][0]);
            acc[1][1] = fma2(pr[dk + 2], w01.y, acc[1][1]);
            acc[2][0] = fma2(pr[dk], w23.x, acc[2][0]);
            acc[2][1] = fma2(pr[dk + 2], w23.x, acc[2][1]);
            acc[3][0] = fma2(pr[dk], w23.y, acc[3][0]);
            acc[3][1] = fma2(pr[dk + 2], w23.y, acc[3][1]);
        }
    }

    // epilogue: STG.128 pre-BN outputs + per-channel stats partials
#pragma unroll
    for (int co = 0; co < CO; co++) {
        float* op = out + (((size_t)km * B_ + b) * COUT + co0 + co) * T_ + t0;
        float2 a0 = u2f(acc[co][0]), a1 = u2f(acc[co][1]);
        *reinterpret_cast<float4*>(op + tb) = make_float4(a0.x, a0.y, a1.x, a1.y);
        ull ssum = add2(acc[co][0], acc[co][1]);
        ull qsum = fma2(acc[co][0], acc[co][0], (ull)0);
        qsum = fma2(acc[co][1], acc[co][1], qsum);
        float2 fs = u2f(ssum), fq = u2f(qsum);
        float s = fs.x + fs.y;
        float q = fq.x + fq.y;
#pragma unroll
        for (int o = G / 2; o > 0; o >>= 1) {
            s += __shfl_down_sync(0xffffffffu, s, o, G);
            q += __shfl_down_sync(0xffffffffu, q, o, G);
        }
        if (h == 0) {
            size_t pidx = ((size_t)(km * COUT + co0 + co) * B_ + b) * NB
                          + blockIdx.x;
            psum[pidx] = s;
            psq[pidx] = q;
        }
    }
}

// ---------------------------------------------------------------------------
// 4. BN statistics finalize: one block per (km, ch), sums B*nblk partials.
// ---------------------------------------------------------------------------
__global__ __launch_bounds__(256) void stats_fin_kernel(int Cout, int nblk) {
    int co = blockIdx.x, km = blockIdx.y;
    int tid = threadIdx.x;
    const float* ps = d_psum + (size_t)(km * Cout + co) * B_ * nblk;
    const float* pq = d_psq + (size_t)(km * Cout + co) * B_ * nblk;
    float s = 0.f, q = 0.f;
    for (int i = tid; i < B_ * nblk; i += 256) {
        s += ps[i];
        q += pq[i];
    }
    __shared__ float r1[256], r2[256];
    r1[tid] = s; r2[tid] = q;
    __syncthreads();
    for (int o = 128; o > 0; o >>= 1) {
        if (tid < o) { r1[tid] += r1[tid + o]; r2[tid] += r2[tid + o]; }
        __syncthreads();
    }
    if (tid == 0) {
        float cnt = (float)B_ * (float)T_;
        float m = r1[0] / cnt;
        float v = r2[0] / cnt - m * m;
        d_mean[km * 64 + co] = m;
        d_rstd[km * 64 + co] = rsqrtf(v + EPS_);
    }
}

// ---------------------------------------------------------------------------
// 5. BN+ReLU + mean-pool over T -> feats (B, K*FEAT)
// ---------------------------------------------------------------------------
__global__ __launch_bounds__(256) void pool_kernel(
    const float* __restrict__ h,
    const float* __restrict__ bng, const float* __restrict__ bnb) {
    int co = blockIdx.x, b = blockIdx.y, km = blockIdx.z;
    int tid = threadIdx.x;
    float a = bng[km * FEAT_ + co] * d_rstd[km * 64 + co];
    float cc = bnb[km * FEAT_ + co] - a * d_mean[km * 64 + co];
    const float* row = h + (((size_t)km * B_ + b) * FEAT_ + co) * T_;
    float s = 0.f;
    for (int t = tid; t < T_; t += 256)
        s += fmaxf(fmaf(a, row[t], cc), 0.f);
    __shared__ float r[256];
    r[tid] = s;
    __syncthreads();
    for (int o = 128; o > 0; o >>= 1) {
        if (tid < o) r[tid] += r[tid + o];
        __syncthreads();
    }
    if (tid == 0)
        d_feats[(size_t)b * (K_ * FEAT_) + km * FEAT_ + co] = r[0] * (1.0f / T_);
}

// ---------------------------------------------------------------------------
// 6. Classifier: relu(fused @ fc1^T + b1) @ fc2^T + b2
// ---------------------------------------------------------------------------
__global__ __launch_bounds__(128) void classifier_kernel(
    const float* __restrict__ w1, const float* __restrict__ b1,
    const float* __restrict__ w2, const float* __restrict__ b2,
    float* __restrict__ out) {
    int b = blockIdx.x;
    int j = threadIdx.x;
    __shared__ float sf[K_ * FEAT_];
    __shared__ float sh[HID_];
    for (int i = j; i < K_ * FEAT_; i += 128) sf[i] = d_feats[(size_t)b * (K_ * FEAT_) + i];
    __syncthreads();
    float a = b1[j];
    const float* wr = w1 + (size_t)j * (K_ * FEAT_);
#pragma unroll 8
    for (int i = 0; i < K_ * FEAT_; i++) a = fmaf(sf[i], wr[i], a);
    sh[j] = fmaxf(a, 0.f);
    __syncthreads();
    if (j < NCLS_) {
        float o = b2[j];
        const float* w2r = w2 + (size_t)j * HID_;
#pragma unroll 8
        for (int i = 0; i < HID_; i++) o = fmaf(sh[i], w2r[i], o);
        out[b * NCLS_ + j] = o;
    }
}

// ---------------------------------------------------------------------------
// Launch
// ---------------------------------------------------------------------------
extern "C" void kernel_launch(void* const* d_in, const int* in_sizes, int n_in,
                              void* d_out, int out_size) {
    const float* x         = (const float*)d_in[0];
    const float* log_alpha = (const float*)d_in[1];
    const float* raw_tau   = (const float*)d_in[2];
    const float* raw_omega = (const float*)d_in[3];
    const float* conv_w1   = (const float*)d_in[4];
    const float* conv_b1   = (const float*)d_in[5];
    const float* bn_g1     = (const float*)d_in[6];
    const float* bn_b1     = (const float*)d_in[7];
    const float* conv_w2   = (const float*)d_in[8];
    const float* conv_b2   = (const float*)d_in[9];
    const float* bn_g2     = (const float*)d_in[10];
    const float* bn_b2     = (const float*)d_in[11];
    const float* conv_w3   = (const float*)d_in[12];
    const float* conv_b3   = (const float*)d_in[13];
    const float* bn_g3     = (const float*)d_in[14];
    const float* bn_b3     = (const float*)d_in[15];
    const float* fc1_w     = (const float*)d_in[16];
    const float* fc1_b     = (const float*)d_in[17];
    const float* fc2_w     = (const float*)d_in[18];
    const float* fc2_b     = (const float*)d_in[19];
    float* out = (float*)d_out;

    float *p_modes, *p_h1, *p_h2, *p_h3, *p_mean, *p_rstd, *p_psum, *p_psq;
    ull *p_w21, *p_w22, *p_w23;
    cudaGetSymbolAddress((void**)&p_modes, d_modes);
    cudaGetSymbolAddress((void**)&p_h1, d_h1);
    cudaGetSymbolAddress((void**)&p_h2, d_h2);
    cudaGetSymbolAddress((void**)&p_h3, d_h3);
    cudaGetSymbolAddress((void**)&p_mean, d_mean);
    cudaGetSymbolAddress((void**)&p_rstd, d_rstd);
    cudaGetSymbolAddress((void**)&p_psum, d_psum);
    cudaGetSymbolAddress((void**)&p_psq, d_psq);
    cudaGetSymbolAddress((void**)&p_w21, d_w2_1);
    cudaGetSymbolAddress((void**)&p_w22, d_w2_2);
    cudaGetSymbolAddress((void**)&p_w23, d_w2_3);

    // #1 UVMD filters
    g_kernel<<<(TR_ + 127) / 128, 128>>>(log_alpha, raw_tau, raw_omega);
    // #2 FFT -> filter -> iFFT -> modes
    uvmd_kernel<<<B_ * C_, 256>>>(x);
    // #3 weight repack
    wprep_kernel<<<(K_ * 64 * 64 * 3 + 255) / 256, 256>>>(conv_w1, conv_w2, conv_w3);

    // #4 conv1: 12 -> 32, k=7, TILE=128 (G=32, 8 co-groups)
    conv_kernel<12, 32, 7, 128, 16><<<dim3(16, B_, K_), 256>>>(
        p_modes, p_w21, conv_b1, nullptr, nullptr, nullptr, nullptr,
        p_h1, p_psum, p_psq, 0);
    // #5 finalize BN1
    stats_fin_kernel<<<dim3(32, K_), 256>>>(32, 16);
    // #6 conv2: 32 -> 64, k=5, TILE=64 (G=16, 16 co-groups)  <-- ncu target
    conv_kernel<32, 64, 5, 64, 32><<<dim3(32, B_, K_), 256>>>(
        p_h1, p_w22, conv_b2, bn_g1, bn_b1, p_mean, p_rstd,
        p_h2, p_psum, p_psq, 1);
    stats_fin_kernel<<<dim3(64, K_), 256>>>(64, 32);
    // conv3: 64 -> 64, k=3, TILE=64
    conv_kernel<64, 64, 3, 64, 32><<<dim3(32, B_, K_), 256>>>(
        p_h2, p_w23, conv_b3, bn_g2, bn_b2, p_mean, p_rstd,
        p_h3, p_psum, p_psq, 1);
    stats_fin_kernel<<<dim3(64, K_), 256>>>(64, 32);
    // BN3+ReLU + mean pool
    pool_kernel<<<dim3(FEAT_, B_, K_), 256>>>(p_h3, bn_g3, bn_b3);
    // classifier
    classifier_kernel<<<B_, HID_>>>(fc1_w, fc1_b, fc2_w, fc2_b, out);
}

// round 9
// speedup vs baseline: 1.0555x; 1.0555x over previous
#include <cuda_runtime.h>
#include <cuda_bf16.h>
#include <math.h>
#include <stdint.h>

// Problem constants
#define B_ 256
#define T_ 2048
#define C_ 12
#define K_ 4
#define L_ 8
#define FEAT_ 64
#define HID_ 128
#define NCLS_ 10
#define N2_ 1024
#define TR_ 1025
#define EPS_ 1e-5f
#define NBMAX_ 32

typedef unsigned long long ull;

// ---------------------------------------------------------------------------
// Device scratch (static; no runtime allocation)
// ---------------------------------------------------------------------------
__device__ float g_filt[K_ * TR_];
__device__ float d_modes[(size_t)K_ * B_ * C_ * T_];             // 96 MB
__device__ float d_h1[(size_t)K_ * B_ * 32 * T_];                // 256 MB
__device__ float d_h2[(size_t)K_ * B_ * 64 * T_];                // 512 MB
__device__ float d_h3[(size_t)K_ * B_ * 64 * T_];                // 512 MB
__device__ float d_psum[(size_t)K_ * 64 * B_ * NBMAX_];
__device__ float d_psq[(size_t)K_ * 64 * B_ * NBMAX_];
__device__ float d_mean[K_ * 64];
__device__ float d_rstd[K_ * 64];
__device__ float d_feats[B_ * K_ * FEAT_];
// weight pairs (w,w), layout [km][ci*KS+dk][co]
__device__ __align__(16) ull d_w2_1[K_ * 12 * 7 * 32];
__device__ __align__(16) ull d_w2_2[K_ * 32 * 5 * 64];
__device__ __align__(16) ull d_w2_3[K_ * 64 * 3 * 64];

// ---------------------------------------------------------------------------
// Packed f32x2 helpers
// ---------------------------------------------------------------------------
__device__ __forceinline__ ull pack2(float lo, float hi) {
    ull r; asm("mov.b64 %0, {%1, %2};" : "=l"(r) : "f"(lo), "f"(hi)); return r;
}
__device__ __forceinline__ float2 u2f(ull v) {
    float2 f; asm("mov.b64 {%0, %1}, %2;" : "=f"(f.x), "=f"(f.y) : "l"(v)); return f;
}
__device__ __forceinline__ ull fma2(ull a, ull b, ull c) {
    ull d; asm("fma.rn.f32x2 %0, %1, %2, %3;" : "=l"(d) : "l"(a), "l"(b), "l"(c)); return d;
}
__device__ __forceinline__ ull add2(ull a, ull b) {
    ull d; asm("add.rn.f32x2 %0, %1, %2;" : "=l"(d) : "l"(a), "l"(b)); return d;
}

// ---------------------------------------------------------------------------
// 1. UVMD frequency-domain filters g_k(f) (scan is linear in f_hat).
// ---------------------------------------------------------------------------
__device__ __forceinline__ float softplusf(float x) {
    if (x > 20.f) return x;
    return log1pf(expf(x));
}

__global__ __launch_bounds__(128) void g_kernel(
        const float* __restrict__ log_alpha,
        const float* __restrict__ raw_tau,
        const float* __restrict__ raw_omega) {
    float om[K_];
#pragma unroll
    for (int k = 0; k < K_; k++) om[k] = 0.5f / (1.0f + expf(-raw_omega[k]));
    int f = blockIdx.x * blockDim.x + threadIdx.x;
    if (f >= TR_) return;
    float fr = 0.5f * (float)f / 1024.0f;
    float u[K_] = {0.f, 0.f, 0.f, 0.f};
    float lam = 0.f;
    for (int l = 0; l < L_; l++) {
        float tau_l = softplusf(raw_tau[l]);
        float us = u[0] + u[1] + u[2] + u[3];
        float nu[K_], ns = 0.f;
#pragma unroll
        for (int k = 0; k < K_; k++) {
            float a = expf(log_alpha[l * K_ + k]);
            float d = fr - om[k];
            float num = 1.0f - (us - u[k]) + 0.5f * lam;
            nu[k] = num / (1.0f + 2.0f * a * d * d);
            ns += nu[k];
        }
#pragma unroll
        for (int k = 0; k < K_; k++) u[k] = nu[k];
        lam += tau_l * (1.0f - ns);
    }
#pragma unroll
    for (int k = 0; k < K_; k++) g_filt[k * TR_ + f] = u[k];
}

// ---------------------------------------------------------------------------
// 2. Fused rfft -> filter -> irfft per (b,c) signal; writes modes (K,B,C,T).
// ---------------------------------------------------------------------------
__device__ __forceinline__ void fft1024(float* zr, float* zi,
                                        const float* twr, const float* twi,
                                        float dir, int tid) {
#pragma unroll
    for (int s = 0; s < 10; s++) {
        int half = 1 << s;
        int shift = 9 - s;
#pragma unroll
        for (int rep = 0; rep < 2; rep++) {
            int i = tid + rep * 256;
            int pos = i & (half - 1);
            int blk = i >> s;
            int i1 = (blk << (s + 1)) + pos;
            int i2 = i1 + half;
            int ti = pos << shift;
            float c = twr[ti];
            float sn = dir * twi[ti];
            float x2r = zr[i2], x2i = zi[i2];
            float tr = c * x2r - sn * x2i;
            float tim = sn * x2r + c * x2i;
            float x1r = zr[i1], x1i = zi[i1];
            zr[i2] = x1r - tr; zi[i2] = x1i - tim;
            zr[i1] = x1r + tr; zi[i1] = x1i + tim;
        }
        __syncthreads();
    }
}

__global__ __launch_bounds__(256) void uvmd_kernel(const float* __restrict__ x) {
    __shared__ float twr[512], twi[512];
    __shared__ float zr[N2_], zi[N2_];
    __shared__ float Xr[TR_], Xi[TR_];
    int tid = threadIdx.x;
    int sig = blockIdx.x;
    int b = sig / C_, c = sig % C_;

    for (int j = tid; j < 512; j += 256) {
        float ang = (float)M_PI * (float)j / 512.0f;
        twr[j] = cosf(ang);
        twi[j] = -sinf(ang);
    }
    const float* xb = x + (size_t)b * T_ * C_ + c;
    for (int n = tid; n < N2_; n += 256) {
        int j = __brev((unsigned)n) >> 22;
        zr[n] = xb[(size_t)(2 * j) * C_];
        zi[n] = xb[(size_t)(2 * j + 1) * C_];
    }
    __syncthreads();
    fft1024(zr, zi, twr, twi, 1.0f, tid);

    for (int k = tid; k < N2_; k += 256) {
        if (k == 0) {
            Xr[0] = zr[0] + zi[0];   Xi[0] = 0.f;
            Xr[N2_] = zr[0] - zi[0]; Xi[N2_] = 0.f;
        } else {
            float ar = zr[k], ai = zi[k];
            float br = zr[N2_ - k], bi = -zi[N2_ - k];
            float er = 0.5f * (ar + br), ei = 0.5f * (ai + bi);
            float dr = 0.5f * (ar - br), di = 0.5f * (ai - bi);
            float or_ = di, oi = -dr;
            float s_, c_;
            __sincosf(-(float)M_PI * (float)k / 1024.0f, &s_, &c_);
            Xr[k] = er + c_ * or_ - s_ * oi;
            Xi[k] = ei + s_ * or_ + c_ * oi;
        }
    }
    __syncthreads();

    const float invn = 1.0f / 1024.0f;
    for (int km = 0; km < K_; km++) {
        const float* g = g_filt + km * TR_;
        for (int n = tid; n < N2_; n += 256) {
            int k = __brev((unsigned)n) >> 22;
            float vr, vi;
            if (k == 0) {
                float y0 = g[0] * Xr[0];
                float y1 = g[N2_] * Xr[N2_];
                vr = 0.5f * (y0 + y1);
                vi = 0.5f * (y0 - y1);
            } else {
                float gk = g[k], gm = g[N2_ - k];
                float yr = gk * Xr[k], yi = gk * Xi[k];
                float mr = gm * Xr[N2_ - k], mi = -(gm * Xi[N2_ - k]);
                float er = 0.5f * (yr + mr), ei = 0.5f * (yi + mi);
                float dr = 0.5f * (yr - mr), di = 0.5f * (yi - mi);
                float s_, c_;
                __sincosf((float)M_PI * (float)k / 1024.0f, &s_, &c_);
                float or_ = c_ * dr - s_ * di;
                float oi  = s_ * dr + c_ * di;
                vr = er - oi;
                vi = ei + or_;
            }
            zr[n] = vr; zi[n] = vi;
        }
        __syncthreads();
        fft1024(zr, zi, twr, twi, -1.0f, tid);
        float* orow = d_modes + ((((size_t)km * B_ + b) * C_ + c)) * T_;
        for (int n = tid; n < N2_; n += 256) {
            float2 v = make_float2(zr[n] * invn, zi[n] * invn);
            *reinterpret_cast<float2*>(orow + 2 * n) = v;
        }
        __syncthreads();
    }
}

// ---------------------------------------------------------------------------
// 2b. Weight repack: (w,w) pairs in layout [km][ci*KS+dk][co].
// ---------------------------------------------------------------------------
template <int CIN, int COUT, int KS>
__device__ __forceinline__ void wrepack_one(const float* __restrict__ w,
                                            ull* __restrict__ dst, int i) {
    const int n = K_ * CIN * KS * COUT;
    if (i >= n) return;
    int km = i / (CIN * KS * COUT);
    int r = i % (CIN * KS * COUT);
    int tap = r / COUT;
    int co = r % COUT;
    int ci = tap / KS;
    int dk = tap % KS;
    float v = w[(((size_t)km * COUT + co) * CIN + ci) * KS + dk];
    dst[i] = pack2(v, v);
}

__global__ __launch_bounds__(256) void wprep_kernel(
    const float* __restrict__ w1, const float* __restrict__ w2,
    const float* __restrict__ w3) {
    int i = blockIdx.x * blockDim.x + threadIdx.x;
    wrepack_one<12, 32, 7>(w1, d_w2_1, i);
    wrepack_one<32, 64, 5>(w2, d_w2_2, i);
    wrepack_one<64, 64, 3>(w3, d_w2_3, i);
}

// ---------------------------------------------------------------------------
// 3. Conv1d: CO=8 output channels x 4 t per thread. Each weight LDG.128
//    feeds 2 channels x 2 pairs of fma2 -> weight-load issue amortized 2x
//    vs CO=4 (the r8 L1 bottleneck). Window via 2-3 LDS.128 (16B-aligned),
//    operand pairs pr[j] packed once on the ALU pipe.
//    Fused input BN+ReLU + fused per-warp BN-stat partials.
//    blockDim = 256 = (COUT/8) * (TILE/4). gridDim = (T/TILE, B, K).
// ---------------------------------------------------------------------------
template <int CIN, int COUT, int KS, int TILE, int NB>
__global__ __launch_bounds__(256) void conv_kernel(
    const float* __restrict__ in, const ull* __restrict__ w2g,
    const float* __restrict__ bias,
    const float* __restrict__ bng, const float* __restrict__ bnb,
    const float* __restrict__ mean, const float* __restrict__ rstd,
    float* __restrict__ out, float* __restrict__ psum, float* __restrict__ psq,
    int apply_bn)
{
    constexpr int CO = 8;
    constexpr int PAD = KS / 2;
    constexpr int G = TILE / 4;           // threads per co-group
    constexpr int NG = COUT / CO;         // co-groups
    static_assert(G * NG == 256, "block size");
    constexpr int WPG = G / 32;           // warps per co-group (1 or 2)
    constexpr int IW = TILE + KS - 1;
    constexpr int IWP = TILE + 16;        // padded row stride (floats)
    constexpr int NF4 = (KS + 6) / 4;     // float4 loads (window KS+3 floats)
    constexpr int NPR = KS + 2;           // operand pairs pr[j]=(f[j],f[j+1])
    __shared__ __align__(16) float s_in[CIN][IWP];
    __shared__ float s_a[CIN], s_c[CIN];

    int tx = threadIdx.x;
    int b = blockIdx.y;
    int km = blockIdx.z;
    int t0 = blockIdx.x * TILE;
    const float* inb = in + (((size_t)km * B_ + b) * CIN) * T_;

    if (apply_bn) {
        for (int ci = tx; ci < CIN; ci += 256) {
            float a = bng[km * CIN + ci] * rstd[km * 64 + ci];
            s_a[ci] = a;
            s_c[ci] = bnb[km * CIN + ci] - a * mean[km * 64 + ci];
        }
        __syncthreads();
    }
    for (int idx = tx; idx < CIN * IW; idx += 256) {
        int ci = idx / IW, tl = idx % IW;
        int t = t0 + tl - PAD;
        float v = 0.f;
        if (t >= 0 && t < T_) {
            v = inb[(size_t)ci * T_ + t];
            if (apply_bn) v = fmaxf(fmaf(s_a[ci], v, s_c[ci]), 0.f);
        }
        s_in[ci][tl] = v;
    }
    __syncthreads();

    int h = tx % G;
    int cog = tx / G;
    int co0 = cog * CO;
    int tb = 4 * h;                       // local float base (16B aligned)

    ull acc[CO][2];
#pragma unroll
    for (int co = 0; co < CO; co++) {
        float bsv = bias[km * COUT + co0 + co];
        acc[co][0] = pack2(bsv, bsv);
        acc[co][1] = acc[co][0];
    }

    const ull* wb = w2g + (size_t)km * CIN * KS * COUT + co0;
    for (int ci = 0; ci < CIN; ci++) {
        float f[NF4 * 4];
        const float4* p = reinterpret_cast<const float4*>(&s_in[ci][tb]);
#pragma unroll
        for (int q = 0; q < NF4; q++) {
            float4 v = p[q];
            f[4 * q] = v.x; f[4 * q + 1] = v.y;
            f[4 * q + 2] = v.z; f[4 * q + 3] = v.w;
        }
        ull pr[NPR];
#pragma unroll
        for (int j = 0; j < NPR; j++) pr[j] = pack2(f[j], f[j + 1]);
        const ull* wci = wb + (size_t)ci * KS * COUT;
#pragma unroll
        for (int dk = 0; dk < KS; dk++) {
            ulonglong2 w01 = __ldg(reinterpret_cast<const ulonglong2*>(
                wci + (size_t)dk * COUT));
            ulonglong2 w23 = __ldg(reinterpret_cast<const ulonglong2*>(
                wci + (size_t)dk * COUT + 2));
            ulonglong2 w45 = __ldg(reinterpret_cast<const ulonglong2*>(
                wci + (size_t)dk * COUT + 4));
            ulonglong2 w67 = __ldg(reinterpret_cast<const ulonglong2*>(
                wci + (size_t)dk * COUT + 6));
            ull p0 = pr[dk], p1 = pr[dk + 2];
            acc[0][0] = fma2(p0, w01.x, acc[0][0]);
            acc[0][1] = fma2(p1, w01.x, acc[0][1]);
            acc[1][0] = fma2(p0, w01.y, acc[1][0]);
            acc[1][1] = fma2(p1, w01.y, acc[1][1]);
            acc[2][0] = fma2(p0, w23.x, acc[2][0]);
            acc[2][1] = fma2(p1, w23.x, acc[2][1]);
            acc[3][0] = fma2(p0, w23.y, acc[3][0]);
            acc[3][1] = fma2(p1, w23.y, acc[3][1]);
            acc[4][0] = fma2(p0, w45.x, acc[4][0]);
            acc[4][1] = fma2(p1, w45.x, acc[4][1]);
            acc[5][0] = fma2(p0, w45.y, acc[5][0]);
            acc[5][1] = fma2(p1, w45.y, acc[5][1]);
            acc[6][0] = fma2(p0, w67.x, acc[6][0]);
            acc[6][1] = fma2(p1, w67.x, acc[6][1]);
            acc[7][0] = fma2(p0, w67.y, acc[7][0]);
            acc[7][1] = fma2(p1, w67.y, acc[7][1]);
        }
    }

    // epilogue: STG.128 pre-BN outputs + per-warp per-channel stats partials
#pragma unroll
    for (int co = 0; co < CO; co++) {
        float* op = out + (((size_t)km * B_ + b) * COUT + co0 + co) * T_ + t0;
        float2 a0 = u2f(acc[co][0]), a1 = u2f(acc[co][1]);
        *reinterpret_cast<float4*>(op + tb) = make_float4(a0.x, a0.y, a1.x, a1.y);
        ull ssum = add2(acc[co][0], acc[co][1]);
        ull qsum = fma2(acc[co][0], acc[co][0], (ull)0);
        qsum = fma2(acc[co][1], acc[co][1], qsum);
        float2 fs = u2f(ssum), fq = u2f(qsum);
        float s = fs.x + fs.y;
        float q = fq.x + fq.y;
#pragma unroll
        for (int o = 16; o > 0; o >>= 1) {
            s += __shfl_down_sync(0xffffffffu, s, o);
            q += __shfl_down_sync(0xffffffffu, q, o);
        }
        if ((h & 31) == 0) {
            size_t pidx = ((size_t)(km * COUT + co0 + co) * B_ + b) * (NB * WPG)
                          + blockIdx.x * WPG + (h >> 5);
            psum[pidx] = s;
            psq[pidx] = q;
        }
    }
}

// ---------------------------------------------------------------------------
// 4. BN statistics finalize: one block per (km, ch), sums B*nblk partials.
// ---------------------------------------------------------------------------
__global__ __launch_bounds__(256) void stats_fin_kernel(int Cout, int nblk) {
    int co = blockIdx.x, km = blockIdx.y;
    int tid = threadIdx.x;
    const float* ps = d_psum + (size_t)(km * Cout + co) * B_ * nblk;
    const float* pq = d_psq + (size_t)(km * Cout + co) * B_ * nblk;
    float s = 0.f, q = 0.f;
    for (int i = tid; i < B_ * nblk; i += 256) {
        s += ps[i];
        q += pq[i];
    }
    __shared__ float r1[256], r2[256];
    r1[tid] = s; r2[tid] = q;
    __syncthreads();
    for (int o = 128; o > 0; o >>= 1) {
        if (tid < o) { r1[tid] += r1[tid + o]; r2[tid] += r2[tid + o]; }
        __syncthreads();
    }
    if (tid == 0) {
        float cnt = (float)B_ * (float)T_;
        float m = r1[0] / cnt;
        float v = r2[0] / cnt - m * m;
        d_mean[km * 64 + co] = m;
        d_rstd[km * 64 + co] = rsqrtf(v + EPS_);
    }
}

// ---------------------------------------------------------------------------
// 5. BN+ReLU + mean-pool over T -> feats (B, K*FEAT)
// ---------------------------------------------------------------------------
__global__ __launch_bounds__(256) void pool_kernel(
    const float* __restrict__ h,
    const float* __restrict__ bng, const float* __restrict__ bnb) {
    int co = blockIdx.x, b = blockIdx.y, km = blockIdx.z;
    int tid = threadIdx.x;
    float a = bng[km * FEAT_ + co] * d_rstd[km * 64 + co];
    float cc = bnb[km * FEAT_ + co] - a * d_mean[km * 64 + co];
    const float* row = h + (((size_t)km * B_ + b) * FEAT_ + co) * T_;
    float s = 0.f;
    for (int t = tid; t < T_; t += 256)
        s += fmaxf(fmaf(a, row[t], cc), 0.f);
    __shared__ float r[256];
    r[tid] = s;
    __syncthreads();
    for (int o = 128; o > 0; o >>= 1) {
        if (tid < o) r[tid] += r[tid + o];
        __syncthreads();
    }
    if (tid == 0)
        d_feats[(size_t)b * (K_ * FEAT_) + km * FEAT_ + co] = r[0] * (1.0f / T_);
}

// ---------------------------------------------------------------------------
// 6. Classifier: relu(fused @ fc1^T + b1) @ fc2^T + b2
// ---------------------------------------------------------------------------
__global__ __launch_bounds__(128) void classifier_kernel(
    const float* __restrict__ w1, const float* __restrict__ b1,
    const float* __restrict__ w2, const float* __restrict__ b2,
    float* __restrict__ out) {
    int b = blockIdx.x;
    int j = threadIdx.x;
    __shared__ float sf[K_ * FEAT_];
    __shared__ float sh[HID_];
    for (int i = j; i < K_ * FEAT_; i += 128) sf[i] = d_feats[(size_t)b * (K_ * FEAT_) + i];
    __syncthreads();
    float a = b1[j];
    const float* wr = w1 + (size_t)j * (K_ * FEAT_);
#pragma unroll 8
    for (int i = 0; i < K_ * FEAT_; i++) a = fmaf(sf[i], wr[i], a);
    sh[j] = fmaxf(a, 0.f);
    __syncthreads();
    if (j < NCLS_) {
        float o = b2[j];
        const float* w2r = w2 + (size_t)j * HID_;
#pragma unroll 8
        for (int i = 0; i < HID_; i++) o = fmaf(sh[i], w2r[i], o);
        out[b * NCLS_ + j] = o;
    }
}

// ---------------------------------------------------------------------------
// Launch
// ---------------------------------------------------------------------------
extern "C" void kernel_launch(void* const* d_in, const int* in_sizes, int n_in,
                              void* d_out, int out_size) {
    const float* x         = (const float*)d_in[0];
    const float* log_alpha = (const float*)d_in[1];
    const float* raw_tau   = (const float*)d_in[2];
    const float* raw_omega = (const float*)d_in[3];
    const float* conv_w1   = (const float*)d_in[4];
    const float* conv_b1   = (const float*)d_in[5];
    const float* bn_g1     = (const float*)d_in[6];
    const float* bn_b1     = (const float*)d_in[7];
    const float* conv_w2   = (const float*)d_in[8];
    const float* conv_b2   = (const float*)d_in[9];
    const float* bn_g2     = (const float*)d_in[10];
    const float* bn_b2     = (const float*)d_in[11];
    const float* conv_w3   = (const float*)d_in[12];
    const float* conv_b3   = (const float*)d_in[13];
    const float* bn_g3     = (const float*)d_in[14];
    const float* bn_b3     = (const float*)d_in[15];
    const float* fc1_w     = (const float*)d_in[16];
    const float* fc1_b     = (const float*)d_in[17];
    const float* fc2_w     = (const float*)d_in[18];
    const float* fc2_b     = (const float*)d_in[19];
    float* out = (float*)d_out;

    float *p_modes, *p_h1, *p_h2, *p_h3, *p_mean, *p_rstd, *p_psum, *p_psq;
    ull *p_w21, *p_w22, *p_w23;
    cudaGetSymbolAddress((void**)&p_modes, d_modes);
    cudaGetSymbolAddress((void**)&p_h1, d_h1);
    cudaGetSymbolAddress((void**)&p_h2, d_h2);
    cudaGetSymbolAddress((void**)&p_h3, d_h3);
    cudaGetSymbolAddress((void**)&p_mean, d_mean);
    cudaGetSymbolAddress((void**)&p_rstd, d_rstd);
    cudaGetSymbolAddress((void**)&p_psum, d_psum);
    cudaGetSymbolAddress((void**)&p_psq, d_psq);
    cudaGetSymbolAddress((void**)&p_w21, d_w2_1);
    cudaGetSymbolAddress((void**)&p_w22, d_w2_2);
    cudaGetSymbolAddress((void**)&p_w23, d_w2_3);

    // #1 UVMD filters
    g_kernel<<<(TR_ + 127) / 128, 128>>>(log_alpha, raw_tau, raw_omega);
    // #2 FFT -> filter -> iFFT -> modes
    uvmd_kernel<<<B_ * C_, 256>>>(x);
    // #3 weight repack
    wprep_kernel<<<(K_ * 64 * 64 * 3 + 255) / 256, 256>>>(conv_w1, conv_w2, conv_w3);

    // #4 conv1: 12 -> 32, k=7, CO=8, TILE=256 (G=64, WPG=2, NB=8)
    conv_kernel<12, 32, 7, 256, 8><<<dim3(8, B_, K_), 256>>>(
        p_modes, p_w21, conv_b1, nullptr, nullptr, nullptr, nullptr,
        p_h1, p_psum, p_psq, 0);
    // #5 finalize BN1 (nblk = NB*WPG = 16)
    stats_fin_kernel<<<dim3(32, K_), 256>>>(32, 16);
    // #6 conv2: 32 -> 64, k=5, CO=8, TILE=128 (G=32, WPG=1, NB=16)  <-- ncu
    conv_kernel<32, 64, 5, 128, 16><<<dim3(16, B_, K_), 256>>>(
        p_h1, p_w22, conv_b2, bn_g1, bn_b1, p_mean, p_rstd,
        p_h2, p_psum, p_psq, 1);
    stats_fin_kernel<<<dim3(64, K_), 256>>>(64, 16);
    // conv3: 64 -> 64, k=3, CO=8, TILE=128
    conv_kernel<64, 64, 3, 128, 16><<<dim3(16, B_, K_), 256>>>(
        p_h2, p_w23, conv_b3, bn_g2, bn_b2, p_mean, p_rstd,
        p_h3, p_psum, p_psq, 1);
    stats_fin_kernel<<<dim3(64, K_), 256>>>(64, 16);
    // BN3+ReLU + mean pool
    pool_kernel<<<dim3(FEAT_, B_, K_), 256>>>(p_h3, bn_g3, bn_b3);
    // classifier
    classifier_kernel<<<B_, HID_>>>(fc1_w, fc1_b, fc2_w, fc2_b, out);
}

// round 10
// speedup vs baseline: 1.3085x; 1.2397x over previous
#include <cuda_runtime.h>
#include <cuda_bf16.h>
#include <math.h>
#include <stdint.h>

// Problem constants
#define B_ 256
#define T_ 2048
#define C_ 12
#define K_ 4
#define L_ 8
#define FEAT_ 64
#define HID_ 128
#define NCLS_ 10
#define N2_ 1024
#define TR_ 1025
#define EPS_ 1e-5f
#define NBMAX_ 32

typedef unsigned long long ull;

// ---------------------------------------------------------------------------
// Device scratch (static; no runtime allocation)
// ---------------------------------------------------------------------------
__device__ float g_filt[K_ * TR_];
__device__ float d_modes[(size_t)K_ * B_ * C_ * T_];             // 96 MB
__device__ float d_h1[(size_t)K_ * B_ * 32 * T_];                // 256 MB
__device__ float d_h2[(size_t)K_ * B_ * 64 * T_];                // 512 MB
__device__ float d_h3[(size_t)K_ * B_ * 64 * T_];                // 512 MB
__device__ float d_psum[(size_t)K_ * 64 * B_ * NBMAX_];
__device__ float d_psq[(size_t)K_ * 64 * B_ * NBMAX_];
__device__ float d_mean[K_ * 64];
__device__ float d_rstd[K_ * 64];
__device__ float d_feats[B_ * K_ * FEAT_];
// weight pairs (w,w), layout [km][ci*KS+dk][co]
__device__ __align__(16) ull d_w2_1[K_ * 12 * 7 * 32];
__device__ __align__(16) ull d_w2_2[K_ * 32 * 5 * 64];
__device__ __align__(16) ull d_w2_3[K_ * 64 * 3 * 64];

// ---------------------------------------------------------------------------
// Packed f32x2 helpers
// ---------------------------------------------------------------------------
__device__ __forceinline__ ull pack2(float lo, float hi) {
    ull r; asm("mov.b64 %0, {%1, %2};" : "=l"(r) : "f"(lo), "f"(hi)); return r;
}
__device__ __forceinline__ ull f2u(float2 v) {
    ull r; asm("mov.b64 %0, {%1, %2};" : "=l"(r) : "f"(v.x), "f"(v.y)); return r;
}
__device__ __forceinline__ float2 u2f(ull v) {
    float2 f; asm("mov.b64 {%0, %1}, %2;" : "=f"(f.x), "=f"(f.y) : "l"(v)); return f;
}
__device__ __forceinline__ ull fma2(ull a, ull b, ull c) {
    ull d; asm("fma.rn.f32x2 %0, %1, %2, %3;" : "=l"(d) : "l"(a), "l"(b), "l"(c)); return d;
}
__device__ __forceinline__ ull add2(ull a, ull b) {
    ull d; asm("add.rn.f32x2 %0, %1, %2;" : "=l"(d) : "l"(a), "l"(b)); return d;
}

// ---------------------------------------------------------------------------
// 1. UVMD frequency-domain filters g_k(f) (scan is linear in f_hat).
// ---------------------------------------------------------------------------
__device__ __forceinline__ float softplusf(float x) {
    if (x > 20.f) return x;
    return log1pf(expf(x));
}

__global__ __launch_bounds__(128) void g_kernel(
        const float* __restrict__ log_alpha,
        const float* __restrict__ raw_tau,
        const float* __restrict__ raw_omega) {
    float om[K_];
#pragma unroll
    for (int k = 0; k < K_; k++) om[k] = 0.5f / (1.0f + expf(-raw_omega[k]));
    int f = blockIdx.x * blockDim.x + threadIdx.x;
    if (f >= TR_) return;
    float fr = 0.5f * (float)f / 1024.0f;
    float u[K_] = {0.f, 0.f, 0.f, 0.f};
    float lam = 0.f;
    for (int l = 0; l < L_; l++) {
        float tau_l = softplusf(raw_tau[l]);
        float us = u[0] + u[1] + u[2] + u[3];
        float nu[K_], ns = 0.f;
#pragma unroll
        for (int k = 0; k < K_; k++) {
            float a = expf(log_alpha[l * K_ + k]);
            float d = fr - om[k];
            float num = 1.0f - (us - u[k]) + 0.5f * lam;
            nu[k] = num / (1.0f + 2.0f * a * d * d);
            ns += nu[k];
        }
#pragma unroll
        for (int k = 0; k < K_; k++) u[k] = nu[k];
        lam += tau_l * (1.0f - ns);
    }
#pragma unroll
    for (int k = 0; k < K_; k++) g_filt[k * TR_ + f] = u[k];
}

// ---------------------------------------------------------------------------
// 2. Fused rfft -> filter -> irfft per (b,c) signal; writes modes (K,B,C,T).
// ---------------------------------------------------------------------------
__device__ __forceinline__ void fft1024(float* zr, float* zi,
                                        const float* twr, const float* twi,
                                        float dir, int tid) {
#pragma unroll
    for (int s = 0; s < 10; s++) {
        int half = 1 << s;
        int shift = 9 - s;
#pragma unroll
        for (int rep = 0; rep < 2; rep++) {
            int i = tid + rep * 256;
            int pos = i & (half - 1);
            int blk = i >> s;
            int i1 = (blk << (s + 1)) + pos;
            int i2 = i1 + half;
            int ti = pos << shift;
            float c = twr[ti];
            float sn = dir * twi[ti];
            float x2r = zr[i2], x2i = zi[i2];
            float tr = c * x2r - sn * x2i;
            float tim = sn * x2r + c * x2i;
            float x1r = zr[i1], x1i = zi[i1];
            zr[i2] = x1r - tr; zi[i2] = x1i - tim;
            zr[i1] = x1r + tr; zi[i1] = x1i + tim;
        }
        __syncthreads();
    }
}

__global__ __launch_bounds__(256) void uvmd_kernel(const float* __restrict__ x) {
    __shared__ float twr[512], twi[512];
    __shared__ float zr[N2_], zi[N2_];
    __shared__ float Xr[TR_], Xi[TR_];
    int tid = threadIdx.x;
    int sig = blockIdx.x;
    int b = sig / C_, c = sig % C_;

    for (int j = tid; j < 512; j += 256) {
        float ang = (float)M_PI * (float)j / 512.0f;
        twr[j] = cosf(ang);
        twi[j] = -sinf(ang);
    }
    const float* xb = x + (size_t)b * T_ * C_ + c;
    for (int n = tid; n < N2_; n += 256) {
        int j = __brev((unsigned)n) >> 22;
        zr[n] = xb[(size_t)(2 * j) * C_];
        zi[n] = xb[(size_t)(2 * j + 1) * C_];
    }
    __syncthreads();
    fft1024(zr, zi, twr, twi, 1.0f, tid);

    for (int k = tid; k < N2_; k += 256) {
        if (k == 0) {
            Xr[0] = zr[0] + zi[0];   Xi[0] = 0.f;
            Xr[N2_] = zr[0] - zi[0]; Xi[N2_] = 0.f;
        } else {
            float ar = zr[k], ai = zi[k];
            float br = zr[N2_ - k], bi = -zi[N2_ - k];
            float er = 0.5f * (ar + br), ei = 0.5f * (ai + bi);
            float dr = 0.5f * (ar - br), di = 0.5f * (ai - bi);
            float or_ = di, oi = -dr;
            float s_, c_;
            __sincosf(-(float)M_PI * (float)k / 1024.0f, &s_, &c_);
            Xr[k] = er + c_ * or_ - s_ * oi;
            Xi[k] = ei + s_ * or_ + c_ * oi;
        }
    }
    __syncthreads();

    const float invn = 1.0f / 1024.0f;
    for (int km = 0; km < K_; km++) {
        const float* g = g_filt + km * TR_;
        for (int n = tid; n < N2_; n += 256) {
            int k = __brev((unsigned)n) >> 22;
            float vr, vi;
            if (k == 0) {
                float y0 = g[0] * Xr[0];
                float y1 = g[N2_] * Xr[N2_];
                vr = 0.5f * (y0 + y1);
                vi = 0.5f * (y0 - y1);
            } else {
                float gk = g[k], gm = g[N2_ - k];
                float yr = gk * Xr[k], yi = gk * Xi[k];
                float mr = gm * Xr[N2_ - k], mi = -(gm * Xi[N2_ - k]);
                float er = 0.5f * (yr + mr), ei = 0.5f * (yi + mi);
                float dr = 0.5f * (yr - mr), di = 0.5f * (yi - mi);
                float s_, c_;
                __sincosf((float)M_PI * (float)k / 1024.0f, &s_, &c_);
                float or_ = c_ * dr - s_ * di;
                float oi  = s_ * dr + c_ * di;
                vr = er - oi;
                vi = ei + or_;
            }
            zr[n] = vr; zi[n] = vi;
        }
        __syncthreads();
        fft1024(zr, zi, twr, twi, -1.0f, tid);
        float* orow = d_modes + ((((size_t)km * B_ + b) * C_ + c)) * T_;
        for (int n = tid; n < N2_; n += 256) {
            float2 v = make_float2(zr[n] * invn, zi[n] * invn);
            *reinterpret_cast<float2*>(orow + 2 * n) = v;
        }
        __syncthreads();
    }
}

// ---------------------------------------------------------------------------
// 2b. Weight repack: (w,w) pairs in layout [km][ci*KS+dk][co].
// ---------------------------------------------------------------------------
template <int CIN, int COUT, int KS>
__device__ __forceinline__ void wrepack_one(const float* __restrict__ w,
                                            ull* __restrict__ dst, int i) {
    const int n = K_ * CIN * KS * COUT;
    if (i >= n) return;
    int km = i / (CIN * KS * COUT);
    int r = i % (CIN * KS * COUT);
    int tap = r / COUT;
    int co = r % COUT;
    int ci = tap / KS;
    int dk = tap % KS;
    float v = w[(((size_t)km * COUT + co) * CIN + ci) * KS + dk];
    dst[i] = pack2(v, v);
}

__global__ __launch_bounds__(256) void wprep_kernel(
    const float* __restrict__ w1, const float* __restrict__ w2,
    const float* __restrict__ w3) {
    int i = blockIdx.x * blockDim.x + threadIdx.x;
    wrepack_one<12, 32, 7>(w1, d_w2_1, i);
    wrepack_one<32, 64, 5>(w2, d_w2_2, i);
    wrepack_one<64, 64, 3>(w3, d_w2_3, i);
}

// ---------------------------------------------------------------------------
// 3. Conv1d (r5 structure): register-blocked CO=4 channels x 8 t per thread,
//    strided pair assignment (thread g owns pairs g, g+G, g+2G, g+3G),
//    f32x2 math, odd pairs packed on the ALU pipe. Fused input BN+ReLU +
//    fused BN-stat partials.
//    blockDim = 256 = (COUT/CO) * G. TILE = 8*G. gridDim = (T/TILE, B, K).
// ---------------------------------------------------------------------------
template <int CIN, int COUT, int KS, int CO, int G, int NB>
__global__ __launch_bounds__(256) void conv_kernel(
    const float* __restrict__ in, const ull* __restrict__ w2g,
    const float* __restrict__ bias,
    const float* __restrict__ bng, const float* __restrict__ bnb,
    const float* __restrict__ mean, const float* __restrict__ rstd,
    float* __restrict__ out, float* __restrict__ psum, float* __restrict__ psq,
    int apply_bn)
{
    constexpr int TT = 8;              // t positions per thread
    constexpr int TILE = G * TT;
    constexpr int PAD = KS / 2;
    constexpr int IW = TILE + KS - 1;
    constexpr int IWP = (IW + 1) & ~1;
    constexpr int NP = (KS + 1) / 2;   // even pairs needed per output pair
    constexpr int NPR = TT / 2;        // output pairs per thread (strided by G)
    static_assert((COUT / CO) * G == 256, "block size");
    __shared__ __align__(16) float s_in[CIN][IWP];
    __shared__ float s_a[CIN], s_c[CIN];

    int tx = threadIdx.x;
    int b = blockIdx.y;
    int km = blockIdx.z;
    int t0 = blockIdx.x * TILE;
    const float* inb = in + (((size_t)km * B_ + b) * CIN) * T_;

    if (apply_bn) {
        for (int ci = tx; ci < CIN; ci += 256) {
            float a = bng[km * CIN + ci] * rstd[km * 64 + ci];
            s_a[ci] = a;
            s_c[ci] = bnb[km * CIN + ci] - a * mean[km * 64 + ci];
        }
        __syncthreads();
    }
    for (int idx = tx; idx < CIN * IW; idx += 256) {
        int ci = idx / IW, tl = idx % IW;
        int t = t0 + tl - PAD;
        float v = 0.f;
        if (t >= 0 && t < T_) {
            v = inb[(size_t)ci * T_ + t];
            if (apply_bn) v = fmaxf(fmaf(s_a[ci], v, s_c[ci]), 0.f);
        }
        s_in[ci][tl] = v;
    }
    __syncthreads();

    int cog = tx / G;                  // co-group (CO channels)
    int g = tx % G;                    // strided pair lane
    int co0 = cog * CO;

    ull acc[CO][NPR];
#pragma unroll
    for (int co = 0; co < CO; co++) {
        float bsv = bias[km * COUT + co0 + co];
        ull bi = pack2(bsv, bsv);
#pragma unroll
        for (int p = 0; p < NPR; p++) acc[co][p] = bi;
    }

    const ull* wb = w2g + (size_t)km * CIN * KS * COUT + co0;
    for (int ci = 0; ci < CIN; ci++) {
        const float2* srow = reinterpret_cast<const float2*>(&s_in[ci][0]);
        float2 ef[NPR][NP];
#pragma unroll
        for (int i = 0; i < NPR; i++)
#pragma unroll
            for (int j = 0; j < NP; j++) ef[i][j] = srow[g + i * G + j];
        ull ev[NPR][NP], od[NPR][NP - 1];
#pragma unroll
        for (int i = 0; i < NPR; i++) {
#pragma unroll
            for (int j = 0; j < NP; j++) ev[i][j] = f2u(ef[i][j]);
#pragma unroll
            for (int j = 0; j < NP - 1; j++)
                od[i][j] = pack2(ef[i][j].y, ef[i][j + 1].x);
        }
        const ull* wci = wb + (size_t)ci * KS * COUT;
#pragma unroll
        for (int dk = 0; dk < KS; dk++) {
            ull w[CO];
#pragma unroll
            for (int h = 0; h < CO / 2; h++) {
                ulonglong2 wp = __ldg(reinterpret_cast<const ulonglong2*>(
                    wci + (size_t)dk * COUT + 2 * h));
                w[2 * h] = wp.x;
                w[2 * h + 1] = wp.y;
            }
#pragma unroll
            for (int co = 0; co < CO; co++)
#pragma unroll
                for (int i = 0; i < NPR; i++) {
                    ull xv = (dk & 1) ? od[i][(dk - 1) / 2] : ev[i][dk / 2];
                    acc[co][i] = fma2(xv, w[co], acc[co][i]);
                }
        }
    }

    // epilogue: store pre-BN outputs + per-channel stats partials
#pragma unroll
    for (int co = 0; co < CO; co++) {
        float* op = out + (((size_t)km * B_ + b) * COUT + co0 + co) * T_ + t0;
        ull ssum = 0, qsum = 0;        // ull 0 == packed (0.f, 0.f)
#pragma unroll
        for (int i = 0; i < NPR; i++) {
            float2 o = u2f(acc[co][i]);
            *reinterpret_cast<float2*>(op + 2 * (g + i * G)) = o;
            ssum = add2(ssum, acc[co][i]);
            qsum = fma2(acc[co][i], acc[co][i], qsum);
        }
        float2 fs = u2f(ssum), fq = u2f(qsum);
        float s = fs.x + fs.y;
        float q = fq.x + fq.y;
#pragma unroll
        for (int o = G / 2; o > 0; o >>= 1) {
            s += __shfl_down_sync(0xffffffffu, s, o, G);
            q += __shfl_down_sync(0xffffffffu, q, o, G);
        }
        if (g == 0) {
            size_t pidx = ((size_t)(km * COUT + co0 + co) * B_ + b) * NB
                          + blockIdx.x;
            psum[pidx] = s;
            psq[pidx] = q;
        }
    }
}

// ---------------------------------------------------------------------------
// 4. BN statistics finalize: one block per (km, ch), sums B*nblk partials.
// ---------------------------------------------------------------------------
__global__ __launch_bounds__(256) void stats_fin_kernel(int Cout, int nblk) {
    int co = blockIdx.x, km = blockIdx.y;
    int tid = threadIdx.x;
    const float* ps = d_psum + (size_t)(km * Cout + co) * B_ * nblk;
    const float* pq = d_psq + (size_t)(km * Cout + co) * B_ * nblk;
    float s = 0.f, q = 0.f;
    for (int i = tid; i < B_ * nblk; i += 256) {
        s += ps[i];
        q += pq[i];
    }
    __shared__ float r1[256], r2[256];
    r1[tid] = s; r2[tid] = q;
    __syncthreads();
    for (int o = 128; o > 0; o >>= 1) {
        if (tid < o) { r1[tid] += r1[tid + o]; r2[tid] += r2[tid + o]; }
        __syncthreads();
    }
    if (tid == 0) {
        float cnt = (float)B_ * (float)T_;
        float m = r1[0] / cnt;
        float v = r2[0] / cnt - m * m;
        d_mean[km * 64 + co] = m;
        d_rstd[km * 64 + co] = rsqrtf(v + EPS_);
    }
}

// ---------------------------------------------------------------------------
// 5. BN+ReLU + mean-pool over T -> feats (B, K*FEAT)
// ---------------------------------------------------------------------------
__global__ __launch_bounds__(256) void pool_kernel(
    const float* __restrict__ h,
    const float* __restrict__ bng, const float* __restrict__ bnb) {
    int co = blockIdx.x, b = blockIdx.y, km = blockIdx.z;
    int tid = threadIdx.x;
    float a = bng[km * FEAT_ + co] * d_rstd[km * 64 + co];
    float cc = bnb[km * FEAT_ + co] - a * d_mean[km * 64 + co];
    const float* row = h + (((size_t)km * B_ + b) * FEAT_ + co) * T_;
    float s = 0.f;
    for (int t = tid; t < T_; t += 256)
        s += fmaxf(fmaf(a, row[t], cc), 0.f);
    __shared__ float r[256];
    r[tid] = s;
    __syncthreads();
    for (int o = 128; o > 0; o >>= 1) {
        if (tid < o) r[tid] += r[tid + o];
        __syncthreads();
    }
    if (tid == 0)
        d_feats[(size_t)b * (K_ * FEAT_) + km * FEAT_ + co] = r[0] * (1.0f / T_);
}

// ---------------------------------------------------------------------------
// 6. Classifier: relu(fused @ fc1^T + b1) @ fc2^T + b2
// ---------------------------------------------------------------------------
__global__ __launch_bounds__(128) void classifier_kernel(
    const float* __restrict__ w1, const float* __restrict__ b1,
    const float* __restrict__ w2, const float* __restrict__ b2,
    float* __restrict__ out) {
    int b = blockIdx.x;
    int j = threadIdx.x;
    __shared__ float sf[K_ * FEAT_];
    __shared__ float sh[HID_];
    for (int i = j; i < K_ * FEAT_; i += 128) sf[i] = d_feats[(size_t)b * (K_ * FEAT_) + i];
    __syncthreads();
    float a = b1[j];
    const float* wr = w1 + (size_t)j * (K_ * FEAT_);
#pragma unroll 8
    for (int i = 0; i < K_ * FEAT_; i++) a = fmaf(sf[i], wr[i], a);
    sh[j] = fmaxf(a, 0.f);
    __syncthreads();
    if (j < NCLS_) {
        float o = b2[j];
        const float* w2r = w2 + (size_t)j * HID_;
#pragma unroll 8
        for (int i = 0; i < HID_; i++) o = fmaf(sh[i], w2r[i], o);
        out[b * NCLS_ + j] = o;
    }
}

// ---------------------------------------------------------------------------
// Launch
// ---------------------------------------------------------------------------
extern "C" void kernel_launch(void* const* d_in, const int* in_sizes, int n_in,
                              void* d_out, int out_size) {
    const float* x         = (const float*)d_in[0];
    const float* log_alpha = (const float*)d_in[1];
    const float* raw_tau   = (const float*)d_in[2];
    const float* raw_omega = (const float*)d_in[3];
    const float* conv_w1   = (const float*)d_in[4];
    const float* conv_b1   = (const float*)d_in[5];
    const float* bn_g1     = (const float*)d_in[6];
    const float* bn_b1     = (const float*)d_in[7];
    const float* conv_w2   = (const float*)d_in[8];
    const float* conv_b2   = (const float*)d_in[9];
    const float* bn_g2     = (const float*)d_in[10];
    const float* bn_b2     = (const float*)d_in[11];
    const float* conv_w3   = (const float*)d_in[12];
    const float* conv_b3   = (const float*)d_in[13];
    const float* bn_g3     = (const float*)d_in[14];
    const float* bn_b3     = (const float*)d_in[15];
    const float* fc1_w     = (const float*)d_in[16];
    const float* fc1_b     = (const float*)d_in[17];
    const float* fc2_w     = (const float*)d_in[18];
    const float* fc2_b     = (const float*)d_in[19];
    float* out = (float*)d_out;

    float *p_modes, *p_h1, *p_h2, *p_h3, *p_mean, *p_rstd, *p_psum, *p_psq;
    ull *p_w21, *p_w22, *p_w23;
    cudaGetSymbolAddress((void**)&p_modes, d_modes);
    cudaGetSymbolAddress((void**)&p_h1, d_h1);
    cudaGetSymbolAddress((void**)&p_h2, d_h2);
    cudaGetSymbolAddress((void**)&p_h3, d_h3);
    cudaGetSymbolAddress((void**)&p_mean, d_mean);
    cudaGetSymbolAddress((void**)&p_rstd, d_rstd);
    cudaGetSymbolAddress((void**)&p_psum, d_psum);
    cudaGetSymbolAddress((void**)&p_psq, d_psq);
    cudaGetSymbolAddress((void**)&p_w21, d_w2_1);
    cudaGetSymbolAddress((void**)&p_w22, d_w2_2);
    cudaGetSymbolAddress((void**)&p_w23, d_w2_3);

    // #1 UVMD filters
    g_kernel<<<(TR_ + 127) / 128, 128>>>(log_alpha, raw_tau, raw_omega);
    // #2 FFT -> filter -> iFFT -> modes
    uvmd_kernel<<<B_ * C_, 256>>>(x);
    // #3 weight repack
    wprep_kernel<<<(K_ * 64 * 64 * 3 + 255) / 256, 256>>>(conv_w1, conv_w2, conv_w3);

    // #4 conv1: 12 -> 32, k=7, CO=4, G=32 (TILE=256, NB=8)  <-- ncu capture
    conv_kernel<12, 32, 7, 4, 32, 8><<<dim3(8, B_, K_), 256>>>(
        p_modes, p_w21, conv_b1, nullptr, nullptr, nullptr, nullptr,
        p_h1, p_psum, p_psq, 0);
    // #5 finalize BN1
    stats_fin_kernel<<<dim3(32, K_), 256>>>(32, 8);
    // #6 conv2: 32 -> 64, k=5, CO=4, G=16 (TILE=128, NB=16)  [r5-proven]
    conv_kernel<32, 64, 5, 4, 16, 16><<<dim3(16, B_, K_), 256>>>(
        p_h1, p_w22, conv_b2, bn_g1, bn_b1, p_mean, p_rstd,
        p_h2, p_psum, p_psq, 1);
    stats_fin_kernel<<<dim3(64, K_), 256>>>(64, 16);
    // conv3: 64 -> 64, k=3, CO=4, G=16 (TILE=128, NB=16)  [r5-proven]
    conv_kernel<64, 64, 3, 4, 16, 16><<<dim3(16, B_, K_), 256>>>(
        p_h2, p_w23, conv_b3, bn_g2, bn_b2, p_mean, p_rstd,
        p_h3, p_psum, p_psq, 1);
    stats_fin_kernel<<<dim3(64, K_), 256>>>(64, 16);
    // BN3+ReLU + mean pool
    pool_kernel<<<dim3(FEAT_, B_, K_), 256>>>(p_h3, bn_g3, bn_b3);
    // classifier
    classifier_kernel<<<B_, HID_>>>(fc1_w, fc1_b, fc2_w, fc2_b, out);
}